// round 2
// baseline (speedup 1.0000x reference)
#include <cuda_runtime.h>
#include <math.h>

// Problem constants
constexpr int C      = 1024;
constexpr int H      = 64;
constexpr int BM     = 128;     // rows per block
constexpr int XSTR   = 130;     // 128-wide input buffer stride (even, conflict-free)
constexpr int MSTR   = 66;      // 64-wide buffer stride (even, conflict-free)

// Shared memory layout (in floats)
constexpr int OFF_XS   = 0;                    // 128 x 130
constexpr int OFF_HTS  = OFF_XS  + BM * XSTR;  // 128 x 66 (raw ht / later in_)
constexpr int OFF_HS   = OFF_HTS + BM * MSTR;  // 128 x 66 (stage buf)
constexpr int OFF_MS   = OFF_HS  + BM * MSTR;  // 128 x 66 (m / h_next)
constexpr int OFF_WS   = OFF_MS  + BM * MSTR;  // 64 x 130 transposed weights
constexpr int OFF_BN1  = OFF_WS  + 64 * 130;   // 128
constexpr int OFF_BN2  = OFF_BN1 + 128;        // 128
constexpr int OFF_BE   = OFF_BN2 + 128;        // 64
constexpr int OFF_BA   = OFF_BE  + 64;         // 64
constexpr int OFF_BIH  = OFF_BA  + 64;         // 192
constexpr int OFF_BHH  = OFF_BIH + 192;        // 192
constexpr int OFF_WP   = OFF_BHH + 192;        // 64
constexpr int OFF_ADJ  = OFF_WP  + 64;         // 256
constexpr int OFF_EA   = OFF_ADJ + 256;        // 128
constexpr int OFF_MASK = OFF_EA  + 128;        // 128
constexpr int OFF_SH1  = OFF_MASK+ 128;        // 64
constexpr int OFF_INT  = OFF_SH1 + 64;         // mrows(128) + mcount(1)
constexpr int SMEM_FLOATS = OFF_INT + 132;
constexpr int SMEM_BYTES  = SMEM_FLOATS * 4;

// Transposed weight arena (filled once per launch by prep_kernel).
// Layout per stage: [64 cols][K floats] dense, col-major over k.
constexpr int WT_NB1_0 = 0;       // K=128
constexpr int WT_NB2_0 = 8192;    // K=64
constexpr int WT_NB1_1 = 12288;   // K=128
constexpr int WT_NB2_1 = 20480;   // K=64
constexpr int WT_WE    = 24576;   // K=64
constexpr int WT_WA    = 28672;   // K=64
constexpr int WT_R     = 32768;   // K=128 ([Wih_r; Whh_r])
constexpr int WT_Z     = 40960;   // K=128
constexpr int WT_IN    = 49152;   // K=64
constexpr int WT_HN    = 53248;   // K=64
constexpr int WT_TOTAL = 57344;

__device__ float g_adj[2 * C];
__device__ float g_wT[WT_TOTAL];

__device__ __forceinline__ float clip5f(float v) { return fminf(fmaxf(v, -5.f), 5.f); }
__device__ __forceinline__ float sigmf(float v) { return 1.f / (1.f + expf(-v)); }

__device__ __forceinline__ void ffma2(unsigned long long& d, unsigned long long a,
                                      unsigned long long b) {
    asm("fma.rn.f32x2 %0, %1, %2, %0;" : "+l"(d) : "l"(a), "l"(b));
}
__device__ __forceinline__ unsigned long long packlo(float b) {
    return (unsigned long long)__float_as_uint(b);   // {b, 0}
}
__device__ __forceinline__ float accval(unsigned long long a) {
    return __uint_as_float((unsigned)(a & 0xffffffffull)) +
           __uint_as_float((unsigned)(a >> 32));
}

// ---------------- adj precompute ---------------------------------------------------------
__global__ void adj_kernel(const int* __restrict__ qt,
                           const float* __restrict__ onehot,
                           const float* __restrict__ graphs) {
    __shared__ float a0s[C];
    __shared__ float denom_s;
    int d = threadIdx.x;
    int k = blockIdx.x;
    int qt0 = qt[0];
    a0s[d] = onehot[(size_t)qt0 * C + d];
    __syncthreads();
    if (d == 0) {
        float s = 0.f;
        for (int c = 0; c < C; ++c) s += a0s[c];
        denom_s = fmaxf(s, 1.f);
    }
    __syncthreads();
    float s = 0.f;
    for (int c = 0; c < C; ++c) {
        float a = a0s[c];
        if (a != 0.f) s = fmaf(a, graphs[((size_t)k * C + c) * C + d], s);
    }
    g_adj[k * C + d] = clip5f(s / denom_s);
}

// ---------------- weight transpose prep --------------------------------------------------
__global__ void prep_kernel(const float* __restrict__ Wn1, const float* __restrict__ Wn2,
                            const float* __restrict__ We,  const float* __restrict__ Wa,
                            const float* __restrict__ Wih, const float* __restrict__ Whh) {
    int i = blockIdx.x * 256 + threadIdx.x;
    if (i >= WT_TOTAL) return;
    float v;
    if (i < WT_NB2_0)      { int j = i;            int c = j >> 7, k = j & 127; v = Wn1[(size_t)(128 + k) * 64 + c]; }
    else if (i < WT_NB1_1) { int j = i - WT_NB2_0; int c = j >> 6, k = j & 63;  v = Wn2[(size_t)k * 64 + c]; }
    else if (i < WT_NB2_1) { int j = i - WT_NB1_1; int c = j >> 7, k = j & 127; v = Wn1[(size_t)(256 + 128 + k) * 64 + c]; }
    else if (i < WT_WE)    { int j = i - WT_NB2_1; int c = j >> 6, k = j & 63;  v = Wn2[(size_t)(64 + k) * 64 + c]; }
    else if (i < WT_WA)    { int j = i - WT_WE;    int c = j >> 6, k = j & 63;  v = We[(size_t)k * 64 + c]; }
    else if (i < WT_R)     { int j = i - WT_WA;    int c = j >> 6, k = j & 63;  v = Wa[(size_t)k * 64 + c]; }
    else if (i < WT_Z)     { int j = i - WT_R;     int c = j >> 7, k = j & 127;
                             v = (k < 64) ? Wih[(size_t)k * 192 + c] : Whh[(size_t)(k - 64) * 192 + c]; }
    else if (i < WT_IN)    { int j = i - WT_Z;     int c = j >> 7, k = j & 127;
                             v = (k < 64) ? Wih[(size_t)k * 192 + 64 + c] : Whh[(size_t)(k - 64) * 192 + 64 + c]; }
    else if (i < WT_HN)    { int j = i - WT_IN;    int c = j >> 6, k = j & 63;  v = Wih[(size_t)k * 192 + 128 + c]; }
    else                   { int j = i - WT_HN;    int c = j >> 6, k = j & 63;  v = Whh[(size_t)k * 192 + 128 + c]; }
    g_wT[i] = v;
}

// ---------------- staged weight copy (dense [c][K] -> padded [c][WSTR]) ------------------
template <int KD, int WS>
__device__ __forceinline__ void load_wT(float* __restrict__ ws, const float* __restrict__ src) {
    constexpr int per = KD >> 1;
    for (int e = threadIdx.x; e < 64 * per; e += 256) {
        int c = e / per, k2 = e - c * per;
        *(float2*)(ws + c * WS + k2 * 2) = *(const float2*)(src + c * KD + k2 * 2);
    }
}

// ---------------- packed GEMM tile: rows tm+16*rr, cols tn*4+cc --------------------------
template <int KD, int XS, int WS>
__device__ __forceinline__ void gemm2(const float* __restrict__ in, int xOff,
                                      const float* __restrict__ wT,
                                      unsigned long long acc[8][4], int tm, int tn) {
    const float* xb = in + tm * XS + xOff;
    const float* wb = wT + (tn * 4) * WS;
#pragma unroll 4
    for (int k = 0; k < KD; k += 2) {
        unsigned long long w0 = *(const unsigned long long*)(wb + k);
        unsigned long long w1 = *(const unsigned long long*)(wb + WS + k);
        unsigned long long w2 = *(const unsigned long long*)(wb + 2 * WS + k);
        unsigned long long w3 = *(const unsigned long long*)(wb + 3 * WS + k);
#pragma unroll
        for (int rr = 0; rr < 8; ++rr) {
            unsigned long long xv = *(const unsigned long long*)(xb + rr * 16 * XS + k);
            ffma2(acc[rr][0], xv, w0);
            ffma2(acc[rr][1], xv, w1);
            ffma2(acc[rr][2], xv, w2);
            ffma2(acc[rr][3], xv, w3);
        }
    }
}

// ---------------- main fused kernel ------------------------------------------------------
__global__ void __launch_bounds__(256, 1)
fused_kernel(const int* __restrict__ qt, const float* __restrict__ ht,
             const float* __restrict__ onehot, const float* __restrict__ kc,
             const float* __restrict__ nwp,
             const float* __restrict__ Ws1, const float* __restrict__ bs1,
             const float* __restrict__ Ws2, const float* __restrict__ bs2,
             const float* __restrict__ bn1, const float* __restrict__ bn2,
             const float* __restrict__ ea,  const float* __restrict__ be,
             const float* __restrict__ ba,  const float* __restrict__ bih,
             const float* __restrict__ bhh, const float* __restrict__ Wp,
             const float* __restrict__ bp, float* __restrict__ out) {
    extern __shared__ float sm[];
    float* xs   = sm + OFF_XS;
    float* hts  = sm + OFF_HTS;
    float* hs   = sm + OFF_HS;
    float* ms   = sm + OFF_MS;
    float* ws   = sm + OFF_WS;
    float* bn1s = sm + OFF_BN1;
    float* bn2s = sm + OFF_BN2;
    float* bes  = sm + OFF_BE;
    float* bas  = sm + OFF_BA;
    float* bihs = sm + OFF_BIH;
    float* bhhs = sm + OFF_BHH;
    float* Wps  = sm + OFF_WP;
    float* adjs = sm + OFF_ADJ;
    float* eas  = sm + OFF_EA;
    float* masks= sm + OFF_MASK;
    float* sh1  = sm + OFF_SH1;
    int*   mrows  = (int*)(sm + OFF_INT);
    int*   mcount = mrows + 128;

    const int tid = threadIdx.x;
    const int tn  = tid >> 4;    // 0..15, 4 cols each (warp spans 2 tn)
    const int tm  = tid & 15;    // 0..15, rows tm + 16*rr
    const int r0  = blockIdx.x * BM;
    const int b   = r0 >> 10;
    const int c0  = r0 & (C - 1);

    const float nw = fminf(fmaxf(nwp[0], 0.1f), 0.9f);
    const int qtb  = qt[b];

    if (tid == 0) *mcount = 0;

    // ---- load ht tile (raw -> hts, clipped -> xs[:, 0:64]) ----
    const float* htp = ht + (size_t)r0 * H;
    for (int e = tid; e < BM * 16; e += 256) {
        float4 v = *(const float4*)(htp + e * 4);
        int r = e >> 4, h4 = (e & 15) * 4;
        hts[r * MSTR + h4 + 0] = v.x;  hts[r * MSTR + h4 + 1] = v.y;
        hts[r * MSTR + h4 + 2] = v.z;  hts[r * MSTR + h4 + 3] = v.w;
        xs[r * XSTR + h4 + 0] = clip5f(v.x);  xs[r * XSTR + h4 + 1] = clip5f(v.y);
        xs[r * XSTR + h4 + 2] = clip5f(v.z);  xs[r * XSTR + h4 + 3] = clip5f(v.w);
    }
    // ---- kc tile -> xs[:, 64:128] ----
    const float* kcp = kc + (size_t)c0 * H;
    for (int e = tid; e < BM * 16; e += 256) {
        float4 v = *(const float4*)(kcp + e * 4);
        int r = e >> 4, h4 = 64 + (e & 15) * 4;
        xs[r * XSTR + h4 + 0] = clip5f(v.x);  xs[r * XSTR + h4 + 1] = clip5f(v.y);
        xs[r * XSTR + h4 + 2] = clip5f(v.z);  xs[r * XSTR + h4 + 3] = clip5f(v.w);
    }
    // ---- small arrays ----
    if (tid < 64) {
        bn1s[tid] = bn1[tid];      bn1s[64 + tid] = bn1[64 + tid];
        bn2s[tid] = bn2[tid];      bn2s[64 + tid] = bn2[64 + tid];
        bes[tid]  = be[tid];       bas[tid]  = ba[tid];
        Wps[tid]  = Wp[tid];
    }
    if (tid < 192) { bihs[tid] = bih[tid];  bhhs[tid] = bhh[tid]; }
    if (tid < 128) {
        adjs[tid]       = g_adj[c0 + tid];
        adjs[128 + tid] = g_adj[C + c0 + tid];
        eas[tid]        = ea[c0 + tid];
        masks[tid]      = onehot[(size_t)qtb * C + c0 + tid];
    }
    __syncthreads();

    if (tid < 128 && masks[tid] > 0.5f) {
        int p = atomicAdd(mcount, 1);
        mrows[p] = tid;
    }

    // ---- neighbor MLPs ----
#pragma unroll 1
    for (int k = 0; k < 2; ++k) {
        __syncthreads();
        load_wT<128, 130>(ws, g_wT + (k == 0 ? WT_NB1_0 : WT_NB1_1));
        __syncthreads();
        {
            unsigned long long acc[8][4];
#pragma unroll
            for (int rr = 0; rr < 8; ++rr)
#pragma unroll
                for (int cc = 0; cc < 4; ++cc) acc[rr][cc] = packlo(bn1s[k * 64 + tn * 4 + cc]);
            gemm2<128, XSTR, 130>(xs, 0, ws, acc, tm, tn);
#pragma unroll
            for (int rr = 0; rr < 8; ++rr) {
                int row = tm + 16 * rr;
                float2 v0 = make_float2(fmaxf(accval(acc[rr][0]), 0.f), fmaxf(accval(acc[rr][1]), 0.f));
                float2 v1 = make_float2(fmaxf(accval(acc[rr][2]), 0.f), fmaxf(accval(acc[rr][3]), 0.f));
                *(float2*)(hs + row * MSTR + tn * 4)     = v0;
                *(float2*)(hs + row * MSTR + tn * 4 + 2) = v1;
            }
        }
        __syncthreads();
        load_wT<64, 66>(ws, g_wT + (k == 0 ? WT_NB2_0 : WT_NB2_1));
        __syncthreads();
        {
            unsigned long long acc[8][4];
#pragma unroll
            for (int rr = 0; rr < 8; ++rr)
#pragma unroll
                for (int cc = 0; cc < 4; ++cc) acc[rr][cc] = packlo(bn2s[k * 64 + tn * 4 + cc]);
            gemm2<64, MSTR, 66>(hs, 0, ws, acc, tm, tn);
#pragma unroll
            for (int rr = 0; rr < 8; ++rr) {
                int row = tm + 16 * rr;
#pragma unroll
                for (int cc = 0; cc < 4; ++cc) {
                    float nb = fminf(fmaxf(accval(acc[rr][cc]), 0.f), 5.f);
                    float* mp = &ms[row * MSTR + tn * 4 + cc];
                    if (k == 0) *mp = clip5f(adjs[row] * nb);
                    else        *mp = clip5f(nw * (*mp) + (1.f - nw) * adjs[128 + row] * nb);
                }
            }
        }
    }
    __syncthreads();

    // ---- self path for masked rows (rare): overwrite ms[row] with self_feat ----
    int mc = *mcount;
    for (int mi = 0; mi < mc; ++mi) {
        int r = mrows[mi];
        if (tid < 64) {
            float s = bs1[tid];
            for (int i = 0; i < 64; ++i) s = fmaf(hts[r * MSTR + i], Ws1[i * 64 + tid], s);
            for (int i = 0; i < 64; ++i) s = fmaf(xs[r * XSTR + 64 + i], Ws1[(64 + i) * 64 + tid], s);
            sh1[tid] = fmaxf(s, 0.f);
        }
        __syncthreads();
        if (tid < 64) {
            float s = bs2[tid];
            for (int i = 0; i < 64; ++i) s = fmaf(sh1[i], Ws2[i * 64 + tid], s);
            ms[r * MSTR + tid] = fminf(fmaxf(s, 0.f), 10.f);
        }
        __syncthreads();
    }

    // ---- We pass: hs = sigmoid(m @ We + be) ----
    __syncthreads();
    load_wT<64, 66>(ws, g_wT + WT_WE);
    __syncthreads();
    {
        unsigned long long acc[8][4];
#pragma unroll
        for (int rr = 0; rr < 8; ++rr)
#pragma unroll
            for (int cc = 0; cc < 4; ++cc) acc[rr][cc] = packlo(bes[tn * 4 + cc]);
        gemm2<64, MSTR, 66>(ms, 0, ws, acc, tm, tn);
#pragma unroll
        for (int rr = 0; rr < 8; ++rr) {
            int row = tm + 16 * rr;
#pragma unroll
            for (int cc = 0; cc < 4; ++cc)
                hs[row * MSTR + tn * 4 + cc] = sigmf(accval(acc[rr][cc]));
        }
    }

    // ---- Wa pass: res = m - g*hs*m + g*tanh(m@Wa+ba); pack xs = [res | raw ht] ----
    __syncthreads();
    load_wT<64, 66>(ws, g_wT + WT_WA);
    __syncthreads();
    {
        unsigned long long acc[8][4];
#pragma unroll
        for (int rr = 0; rr < 8; ++rr)
#pragma unroll
            for (int cc = 0; cc < 4; ++cc) acc[rr][cc] = packlo(bas[tn * 4 + cc]);
        gemm2<64, MSTR, 66>(ms, 0, ws, acc, tm, tn);
#pragma unroll
        for (int rr = 0; rr < 8; ++rr) {
            int row = tm + 16 * rr;
            float g = eas[row];
#pragma unroll
            for (int cc = 0; cc < 4; ++cc) {
                int j = tn * 4 + cc;
                float m = ms[row * MSTR + j];
                float res = m - g * hs[row * MSTR + j] * m + g * tanhf(accval(acc[rr][cc]));
                xs[row * XSTR + j]      = res;
                xs[row * XSTR + 64 + j] = hts[row * MSTR + j];
            }
        }
    }

    // ---- GRU gate r -> ms ----
    __syncthreads();
    load_wT<128, 130>(ws, g_wT + WT_R);
    __syncthreads();
    {
        unsigned long long acc[8][4];
#pragma unroll
        for (int rr = 0; rr < 8; ++rr)
#pragma unroll
            for (int cc = 0; cc < 4; ++cc)
                acc[rr][cc] = packlo(bihs[tn * 4 + cc] + bhhs[tn * 4 + cc]);
        gemm2<128, XSTR, 130>(xs, 0, ws, acc, tm, tn);
#pragma unroll
        for (int rr = 0; rr < 8; ++rr) {
            int row = tm + 16 * rr;
#pragma unroll
            for (int cc = 0; cc < 4; ++cc)
                ms[row * MSTR + tn * 4 + cc] = sigmf(accval(acc[rr][cc]));
        }
    }

    // ---- GRU gate z -> hs ----
    __syncthreads();
    load_wT<128, 130>(ws, g_wT + WT_Z);
    __syncthreads();
    {
        unsigned long long acc[8][4];
#pragma unroll
        for (int rr = 0; rr < 8; ++rr)
#pragma unroll
            for (int cc = 0; cc < 4; ++cc)
                acc[rr][cc] = packlo(bihs[64 + tn * 4 + cc] + bhhs[64 + tn * 4 + cc]);
        gemm2<128, XSTR, 130>(xs, 0, ws, acc, tm, tn);
#pragma unroll
        for (int rr = 0; rr < 8; ++rr) {
            int row = tm + 16 * rr;
#pragma unroll
            for (int cc = 0; cc < 4; ++cc)
                hs[row * MSTR + tn * 4 + cc] = sigmf(accval(acc[rr][cc]));
        }
    }

    // ---- in_ = res @ Wih_n + b -> hts ----
    __syncthreads();
    load_wT<64, 66>(ws, g_wT + WT_IN);
    __syncthreads();
    {
        unsigned long long acc[8][4];
#pragma unroll
        for (int rr = 0; rr < 8; ++rr)
#pragma unroll
            for (int cc = 0; cc < 4; ++cc) acc[rr][cc] = packlo(bihs[128 + tn * 4 + cc]);
        gemm2<64, XSTR, 66>(xs, 0, ws, acc, tm, tn);
#pragma unroll
        for (int rr = 0; rr < 8; ++rr) {
            int row = tm + 16 * rr;
#pragma unroll
            for (int cc = 0; cc < 4; ++cc)
                hts[row * MSTR + tn * 4 + cc] = accval(acc[rr][cc]);
        }
    }

    // ---- hn pass; fuse n, h_next -> ms ----
    __syncthreads();
    load_wT<64, 66>(ws, g_wT + WT_HN);
    __syncthreads();
    {
        unsigned long long acc[8][4];
#pragma unroll
        for (int rr = 0; rr < 8; ++rr)
#pragma unroll
            for (int cc = 0; cc < 4; ++cc) acc[rr][cc] = packlo(bhhs[128 + tn * 4 + cc]);
        gemm2<64, XSTR, 66>(xs, 64, ws, acc, tm, tn);
#pragma unroll
        for (int rr = 0; rr < 8; ++rr) {
            int row = tm + 16 * rr;
#pragma unroll
            for (int cc = 0; cc < 4; ++cc) {
                int j = tn * 4 + cc;
                float hn  = accval(acc[rr][cc]);
                float r_  = ms[row * MSTR + j];
                float z_  = hs[row * MSTR + j];
                float in_ = hts[row * MSTR + j];
                float n_  = tanhf(in_ + r_ * hn);
                float hp  = xs[row * XSTR + 64 + j];
                ms[row * MSTR + j] = (1.f - z_) * n_ + z_ * hp;
            }
        }
    }
    __syncthreads();

    // ---- y = sigmoid(h_next @ Wp + bp) ----
    if (tid < 128) {
        float s = bp[0];
#pragma unroll
        for (int j = 0; j < 64; ++j) s = fmaf(ms[tid * MSTR + j], Wps[j], s);
        out[r0 + tid] = sigmf(s);
    }
}

// ---------------- launch -----------------------------------------------------------------
extern "C" void kernel_launch(void* const* d_in, const int* in_sizes, int n_in,
                              void* d_out, int out_size) {
    const int*   qt     = (const int*)d_in[1];
    const float* ht     = (const float*)d_in[2];
    const float* onehot = (const float*)d_in[3];
    const float* kc     = (const float*)d_in[4];
    const float* graphs = (const float*)d_in[5];
    const float* nw     = (const float*)d_in[6];
    const float* Ws1    = (const float*)d_in[7];
    const float* bs1    = (const float*)d_in[8];
    const float* Ws2    = (const float*)d_in[9];
    const float* bs2    = (const float*)d_in[10];
    const float* Wn1    = (const float*)d_in[11];
    const float* bn1    = (const float*)d_in[12];
    const float* Wn2    = (const float*)d_in[13];
    const float* bn2    = (const float*)d_in[14];
    const float* ea     = (const float*)d_in[15];
    const float* We     = (const float*)d_in[16];
    const float* be     = (const float*)d_in[17];
    const float* Wa     = (const float*)d_in[18];
    const float* ba     = (const float*)d_in[19];
    const float* Wih    = (const float*)d_in[20];
    const float* bih    = (const float*)d_in[21];
    const float* Whh    = (const float*)d_in[22];
    const float* bhh    = (const float*)d_in[23];
    const float* Wp     = (const float*)d_in[24];
    const float* bp     = (const float*)d_in[25];
    float* out = (float*)d_out;

    cudaFuncSetAttribute(fused_kernel, cudaFuncAttributeMaxDynamicSharedMemorySize, SMEM_BYTES);

    adj_kernel<<<2, 1024>>>(qt, onehot, graphs);
    prep_kernel<<<(WT_TOTAL + 255) / 256, 256>>>(Wn1, Wn2, We, Wa, Wih, Whh);
    fused_kernel<<<(256 * 1024) / BM, 256, SMEM_BYTES>>>(
        qt, ht, onehot, kc, nw, Ws1, bs1, Ws2, bs2, bn1, bn2,
        ea, be, ba, bih, bhh, Wp, bp, out);
}

// round 5
// speedup vs baseline: 2.3845x; 2.3845x over previous
#include <cuda_runtime.h>
#include <cuda_bf16.h>
#include <cstdint>
#include <math.h>

constexpr int C = 1024;

// ---- smem byte offsets ----
constexpr uint32_t XH = 0;          // 128 x 136 halfs (272B rows)
constexpr uint32_t XL = 34816;
constexpr uint32_t YH = 69632;      // 128 x 72 halfs (144B rows)
constexpr uint32_t YL = 88064;
constexpr uint32_t WB0 = 106496;    // weight buffer 0 (up to 36864B)
constexpr uint32_t WB1 = 143360;    // weight buffer 1
constexpr uint32_t MC  = 180224;    // mcount (int)
constexpr uint32_t MR  = 180240;    // mrows 128 ints
constexpr uint32_t S1O = 180752;    // self layer1 (64 f)
constexpr uint32_t SOO = 181008;    // self out (64 f)
constexpr uint32_t SMEM_DYN = 181264 + 16;

constexpr uint32_t XSB = 272;   // X row stride bytes
constexpr uint32_t WSB = 144;   // W/Y row stride bytes

// ---- weight arena stage offsets (bytes); each stage: hi plane (K*144) then lo plane ----
constexpr uint32_t GW1 = 0;        // nb1_0  K128 (36864)
constexpr uint32_t GW2 = 36864;    // nb2_0  K64  (18432)
constexpr uint32_t GW3 = 55296;    // nb1_1  K128
constexpr uint32_t GW4 = 92160;    // nb2_1  K64
constexpr uint32_t GW5 = 110592;   // We     K64
constexpr uint32_t GW6 = 129024;   // Wa     K64
constexpr uint32_t GW7 = 147456;   // GRU r  K128
constexpr uint32_t GW8 = 184320;   // GRU z  K128
constexpr uint32_t GW9 = 221184;   // in     K64
constexpr uint32_t GW10 = 239616;  // hn     K64
__device__ __align__(16) unsigned char g_wb[258048];
__device__ float g_adj[2 * C];

__device__ __forceinline__ float clip5f(float v) { return fminf(fmaxf(v, -5.f), 5.f); }
__device__ __forceinline__ float sigmf(float v) { return 1.f / (1.f + expf(-v)); }

__device__ __forceinline__ uint32_t smem_u32(const void* p) {
    uint32_t a;
    asm("{ .reg .u64 t; cvta.to.shared.u64 t, %1; cvt.u32.u64 %0, t; }" : "=r"(a) : "l"(p));
    return a;
}
__device__ __forceinline__ void ldsm4(uint32_t* r, uint32_t a) {
    asm volatile("ldmatrix.sync.aligned.m8n8.x4.shared.b16 {%0,%1,%2,%3}, [%4];"
                 : "=r"(r[0]), "=r"(r[1]), "=r"(r[2]), "=r"(r[3]) : "r"(a));
}
__device__ __forceinline__ void ldsm4t(uint32_t* r, uint32_t a) {
    asm volatile("ldmatrix.sync.aligned.m8n8.x4.trans.shared.b16 {%0,%1,%2,%3}, [%4];"
                 : "=r"(r[0]), "=r"(r[1]), "=r"(r[2]), "=r"(r[3]) : "r"(a));
}
__device__ __forceinline__ void mma16816(float* d, const uint32_t* a, const uint32_t* b) {
    asm volatile("mma.sync.aligned.m16n8k16.row.col.f32.bf16.bf16.f32 "
                 "{%0,%1,%2,%3}, {%4,%5,%6,%7}, {%8,%9}, {%0,%1,%2,%3};"
                 : "+f"(d[0]), "+f"(d[1]), "+f"(d[2]), "+f"(d[3])
                 : "r"(a[0]), "r"(a[1]), "r"(a[2]), "r"(a[3]), "r"(b[0]), "r"(b[1]));
}
__device__ __forceinline__ void cpa16(uint32_t dst, const void* src) {
    asm volatile("cp.async.cg.shared.global [%0], [%1], 16;" :: "r"(dst), "l"(src));
}
__device__ __forceinline__ void cpa_commit() { asm volatile("cp.async.commit_group;" ::: "memory"); }
__device__ __forceinline__ void cpa_wait0()  { asm volatile("cp.async.wait_group 0;" ::: "memory"); }

// pack fp32 pair -> bf16 hi/lo planes
__device__ __forceinline__ void storePair(uint32_t hiA, uint32_t loA, float f0, float f1) {
    uint32_t h, l;
    asm("cvt.rn.bf16x2.f32 %0, %1, %2;" : "=r"(h) : "f"(f1), "f"(f0));
    float l0 = f0 - __uint_as_float(h << 16);
    float l1 = f1 - __uint_as_float(h & 0xffff0000u);
    asm("cvt.rn.bf16x2.f32 %0, %1, %2;" : "=r"(l) : "f"(l1), "f"(l0));
    asm volatile("st.shared.b32 [%0], %1;" :: "r"(hiA), "r"(h));
    asm volatile("st.shared.b32 [%0], %1;" :: "r"(loA), "r"(l));
}

// ---------------- adj precompute (sparse) ------------------------------------------------
__global__ void adj_kernel(const int* __restrict__ qt, const float* __restrict__ onehot,
                           const float* __restrict__ graphs) {
    __shared__ int nnz;
    __shared__ int idxs[1024];
    __shared__ float wts[1024];
    __shared__ float denom;
    int d = threadIdx.x, k = blockIdx.x;
    const float* a0 = onehot + (size_t)qt[0] * C;
    float a = a0[d];
    if (d == 0) nnz = 0;
    __syncthreads();
    if (a != 0.f) { int p = atomicAdd(&nnz, 1); idxs[p] = d; wts[p] = a; }
    __syncthreads();
    if (d == 0) {
        float s = 0.f;
        for (int i = 0; i < nnz; ++i) s += wts[i];
        denom = fmaxf(s, 1.f);
    }
    __syncthreads();
    float s = 0.f;
    int m = nnz;
    for (int i = 0; i < m; ++i)
        s = fmaf(wts[i], graphs[((size_t)k * C + idxs[i]) * C + d], s);
    g_adj[k * C + d] = clip5f(s / denom);
}

// ---------------- weight prep: padded bf16 hi/lo row-major images ------------------------
__global__ void prep_kernel(const float* __restrict__ Wn1, const float* __restrict__ Wn2,
                            const float* __restrict__ We,  const float* __restrict__ Wa,
                            const float* __restrict__ Wih, const float* __restrict__ Whh) {
    int i = blockIdx.x * 256 + threadIdx.x;
    if (i >= 57344) return;
    int j, K; uint32_t base; float w;
    if (i < 8192)       { j = i;         K = 128; base = GW1;  int k = j >> 6, n = j & 63; w = Wn1[(size_t)(128 + k) * 64 + n]; }
    else if (i < 12288) { j = i - 8192;  K = 64;  base = GW2;  int k = j >> 6, n = j & 63; w = Wn2[(size_t)k * 64 + n]; }
    else if (i < 20480) { j = i - 12288; K = 128; base = GW3;  int k = j >> 6, n = j & 63; w = Wn1[(size_t)(384 + k) * 64 + n]; }
    else if (i < 24576) { j = i - 20480; K = 64;  base = GW4;  int k = j >> 6, n = j & 63; w = Wn2[(size_t)(64 + k) * 64 + n]; }
    else if (i < 28672) { j = i - 24576; K = 64;  base = GW5;  int k = j >> 6, n = j & 63; w = We[(size_t)k * 64 + n]; }
    else if (i < 32768) { j = i - 28672; K = 64;  base = GW6;  int k = j >> 6, n = j & 63; w = Wa[(size_t)k * 64 + n]; }
    else if (i < 40960) { j = i - 32768; K = 128; base = GW7;  int k = j >> 6, n = j & 63;
                          w = (k < 64) ? Wih[(size_t)k * 192 + n] : Whh[(size_t)(k - 64) * 192 + n]; }
    else if (i < 49152) { j = i - 40960; K = 128; base = GW8;  int k = j >> 6, n = j & 63;
                          w = (k < 64) ? Wih[(size_t)k * 192 + 64 + n] : Whh[(size_t)(k - 64) * 192 + 64 + n]; }
    else if (i < 53248) { j = i - 49152; K = 64;  base = GW9;  int k = j >> 6, n = j & 63; w = Wih[(size_t)k * 192 + 128 + n]; }
    else                { j = i - 53248; K = 64;  base = GW10; int k = j >> 6, n = j & 63; w = Whh[(size_t)k * 192 + 128 + n]; }
    int k = j >> 6, n = j & 63;
    __nv_bfloat16 hi = __float2bfloat16(w);
    __nv_bfloat16 lo = __float2bfloat16(w - __bfloat162float(hi));
    *(__nv_bfloat16*)(g_wb + base + (uint32_t)k * WSB + n * 2) = hi;
    *(__nv_bfloat16*)(g_wb + base + (uint32_t)K * WSB + (uint32_t)k * WSB + n * 2) = lo;
}

// ---------------- stage GEMM: D[128,64] = A[128,KD] @ W[KD,64], 3-pass split bf16 --------
template <int KD>
__device__ __forceinline__ void mma_stage(uint32_t aHi, uint32_t aLo, uint32_t aStride,
                                          uint32_t wbuf, float d[8][4], int warp, int lane) {
    const uint32_t wHi = wbuf, wLo = wbuf + KD * WSB;
    const int lrow = (lane & 7) + ((lane & 8) ? 8 : 0);
    const int lhi8 = (lane & 16) ? 8 : 0;
    const uint32_t aHA = aHi + (uint32_t)(warp * 16 + lrow) * aStride + lhi8 * 2;
    const uint32_t aLA = aLo + (uint32_t)(warp * 16 + lrow) * aStride + lhi8 * 2;
    const uint32_t wOff = (uint32_t)lrow * WSB + lhi8 * 2;
#pragma unroll
    for (int kc = 0; kc < KD / 16; ++kc) {
        uint32_t ah[4], al[4], bh[4][4], bl[4][4];
        ldsm4(ah, aHA + kc * 32);
        ldsm4(al, aLA + kc * 32);
#pragma unroll
        for (int p = 0; p < 4; ++p) {
            ldsm4t(bh[p], wHi + wOff + (uint32_t)kc * 16 * WSB + p * 32);
            ldsm4t(bl[p], wLo + wOff + (uint32_t)kc * 16 * WSB + p * 32);
        }
#pragma unroll
        for (int nb = 0; nb < 8; ++nb) {
            const uint32_t* bhp = &bh[nb >> 1][(nb & 1) * 2];
            const uint32_t* blp = &bl[nb >> 1][(nb & 1) * 2];
            mma16816(d[nb], ah, bhp);
            mma16816(d[nb], ah, blp);
            mma16816(d[nb], al, bhp);
        }
    }
}

__device__ __forceinline__ void prefetchW(uint32_t dst, uint32_t gsrc, int bytes, int tid) {
    const unsigned char* s = g_wb + gsrc;
    for (int o = tid * 16; o < bytes; o += 256 * 16) cpa16(dst + o, s + o);
    cpa_commit();
}

// ---------------- main fused kernel ------------------------------------------------------
__global__ void __launch_bounds__(256, 1)
fused_kernel(const int* __restrict__ qt, const float* __restrict__ ht,
             const float* __restrict__ onehot, const float* __restrict__ kc,
             const float* __restrict__ nwp,
             const float* __restrict__ Ws1, const float* __restrict__ bs1,
             const float* __restrict__ Ws2, const float* __restrict__ bs2,
             const float* __restrict__ bn1, const float* __restrict__ bn2,
             const float* __restrict__ ea,  const float* __restrict__ be,
             const float* __restrict__ ba,  const float* __restrict__ bih,
             const float* __restrict__ bhh, const float* __restrict__ Wp,
             const float* __restrict__ bp, float* __restrict__ out) {
    extern __shared__ __align__(16) char sm[];
    const uint32_t smb = smem_u32(sm);

    const int tid = threadIdx.x;
    const int warp = tid >> 5, lane = tid & 31;
    const int q = lane & 3, trow = lane >> 2;
    const int R0 = warp * 16 + trow, R1 = R0 + 8;
    const int r0 = blockIdx.x * 128;
    const int b  = r0 >> 10;
    const int cb0 = r0 & (C - 1);

    int* mcount = (int*)(sm + MC);
    int* mrows  = (int*)(sm + MR);
    float* self1 = (float*)(sm + S1O);
    float* selfo = (float*)(sm + SOO);

    const float nw = fminf(fmaxf(nwp[0], 0.1f), 0.9f);
    const int qtb  = qt[b];
    const float bp0 = bp[0];
    const float adjA0 = g_adj[cb0 + R0], adjA1 = g_adj[cb0 + R1];
    const float adjB0 = g_adj[C + cb0 + R0], adjB1 = g_adj[C + cb0 + R1];
    const float eav0 = ea[cb0 + R0], eav1 = ea[cb0 + R1];
    const float* hp0 = ht + (size_t)(r0 + R0) * 64;
    const float* hp1 = ht + (size_t)(r0 + R1) * 64;

    if (tid == 0) *mcount = 0;
    __syncthreads();
    if (tid < 128 && onehot[(size_t)qtb * C + cb0 + tid] > 0.5f) {
        int p = atomicAdd(mcount, 1);
        mrows[p] = tid;
    }

    // ---- build X = [clip5(ht) | clip5(kc)] bf16 hi/lo planes ----
    {
        int row = tid >> 1, half = tid & 1;
        const float* src = half ? (kc + (size_t)(cb0 + row) * 64) : (ht + (size_t)(r0 + row) * 64);
        uint32_t rowb = (uint32_t)row * XSB + (uint32_t)half * 128;
#pragma unroll
        for (int i = 0; i < 16; ++i) {
            float4 v = ((const float4*)src)[i];
            storePair(smb + XH + rowb + i * 8,     smb + XL + rowb + i * 8,
                      clip5f(v.x), clip5f(v.y));
            storePair(smb + XH + rowb + i * 8 + 4, smb + XL + rowb + i * 8 + 4,
                      clip5f(v.z), clip5f(v.w));
        }
    }
    prefetchW(smb + WB0, GW1, 36864, tid);

    auto stage_sync = [&] { cpa_wait0(); __syncthreads(); };

    float m[8][4], sig[8][4], rg[8][4], zg[8][4], inv[8][4];
    const uint32_t r0off = (uint32_t)R0 * WSB, r1off = (uint32_t)R1 * WSB;

    // ================= stage 1: nb1_0 =================
    stage_sync();
    prefetchW(smb + WB1, GW2, 18432, tid);
    {
        float d[8][4] = {};
        mma_stage<128>(smb + XH, smb + XL, XSB, smb + WB0, d, warp, lane);
#pragma unroll
        for (int nb = 0; nb < 8; ++nb) {
            int c = 8 * nb + 2 * q;
            float b0 = bn1[c], b1 = bn1[c + 1];
            storePair(smb + YH + r0off + c * 2, smb + YL + r0off + c * 2,
                      fmaxf(d[nb][0] + b0, 0.f), fmaxf(d[nb][1] + b1, 0.f));
            storePair(smb + YH + r1off + c * 2, smb + YL + r1off + c * 2,
                      fmaxf(d[nb][2] + b0, 0.f), fmaxf(d[nb][3] + b1, 0.f));
        }
    }
    // ================= stage 2: nb2_0 =================
    stage_sync();
    prefetchW(smb + WB0, GW3, 36864, tid);
    {
        float d[8][4] = {};
        mma_stage<64>(smb + YH, smb + YL, WSB, smb + WB1, d, warp, lane);
#pragma unroll
        for (int nb = 0; nb < 8; ++nb) {
            int c = 8 * nb + 2 * q;
            float b0 = bn2[c], b1 = bn2[c + 1];
            m[nb][0] = clip5f(adjA0 * fminf(fmaxf(d[nb][0] + b0, 0.f), 5.f));
            m[nb][1] = clip5f(adjA0 * fminf(fmaxf(d[nb][1] + b1, 0.f), 5.f));
            m[nb][2] = clip5f(adjA1 * fminf(fmaxf(d[nb][2] + b0, 0.f), 5.f));
            m[nb][3] = clip5f(adjA1 * fminf(fmaxf(d[nb][3] + b1, 0.f), 5.f));
        }
    }
    // ================= stage 3: nb1_1 =================
    stage_sync();
    prefetchW(smb + WB1, GW4, 18432, tid);
    {
        float d[8][4] = {};
        mma_stage<128>(smb + XH, smb + XL, XSB, smb + WB0, d, warp, lane);
#pragma unroll
        for (int nb = 0; nb < 8; ++nb) {
            int c = 8 * nb + 2 * q;
            float b0 = bn1[64 + c], b1 = bn1[64 + c + 1];
            storePair(smb + YH + r0off + c * 2, smb + YL + r0off + c * 2,
                      fmaxf(d[nb][0] + b0, 0.f), fmaxf(d[nb][1] + b1, 0.f));
            storePair(smb + YH + r1off + c * 2, smb + YL + r1off + c * 2,
                      fmaxf(d[nb][2] + b0, 0.f), fmaxf(d[nb][3] + b1, 0.f));
        }
    }
    // ================= stage 4: nb2_1 =================
    stage_sync();
    prefetchW(smb + WB0, GW5, 18432, tid);
    {
        float d[8][4] = {};
        mma_stage<64>(smb + YH, smb + YL, WSB, smb + WB1, d, warp, lane);
        float wn = 1.f - nw;
#pragma unroll
        for (int nb = 0; nb < 8; ++nb) {
            int c = 8 * nb + 2 * q;
            float b0 = bn2[64 + c], b1 = bn2[64 + c + 1];
            m[nb][0] = clip5f(nw * m[nb][0] + wn * adjB0 * fminf(fmaxf(d[nb][0] + b0, 0.f), 5.f));
            m[nb][1] = clip5f(nw * m[nb][1] + wn * adjB0 * fminf(fmaxf(d[nb][1] + b1, 0.f), 5.f));
            m[nb][2] = clip5f(nw * m[nb][2] + wn * adjB1 * fminf(fmaxf(d[nb][2] + b0, 0.f), 5.f));
            m[nb][3] = clip5f(nw * m[nb][3] + wn * adjB1 * fminf(fmaxf(d[nb][3] + b1, 0.f), 5.f));
        }
    }
    // ---- self path for masked rows (rare) ----
    __syncthreads();
    {
        int mc = *mcount;
        for (int mi = 0; mi < mc; ++mi) {
            int rr = mrows[mi];
            if (tid < 64) {
                const float* hrow = ht + (size_t)(r0 + rr) * 64;
                const float* krow = kc + (size_t)(cb0 + rr) * 64;
                float s = bs1[tid];
                for (int i = 0; i < 64; ++i) s = fmaf(hrow[i], Ws1[i * 64 + tid], s);
                for (int i = 0; i < 64; ++i) s = fmaf(krow[i], Ws1[(64 + i) * 64 + tid], s);
                self1[tid] = fmaxf(s, 0.f);
            }
            __syncthreads();
            if (tid < 64) {
                float s = bs2[tid];
                for (int i = 0; i < 64; ++i) s = fmaf(self1[i], Ws2[i * 64 + tid], s);
                selfo[tid] = fminf(fmaxf(s, 0.f), 10.f);
            }
            __syncthreads();
            if (R0 == rr) {
#pragma unroll
                for (int nb = 0; nb < 8; ++nb) {
                    m[nb][0] = selfo[8 * nb + 2 * q];
                    m[nb][1] = selfo[8 * nb + 2 * q + 1];
                }
            }
            if (R1 == rr) {
#pragma unroll
                for (int nb = 0; nb < 8; ++nb) {
                    m[nb][2] = selfo[8 * nb + 2 * q];
                    m[nb][3] = selfo[8 * nb + 2 * q + 1];
                }
            }
            __syncthreads();
        }
    }
    // store m -> Y planes (A operand for We/Wa)
#pragma unroll
    for (int nb = 0; nb < 8; ++nb) {
        int c = 8 * nb + 2 * q;
        storePair(smb + YH + r0off + c * 2, smb + YL + r0off + c * 2, m[nb][0], m[nb][1]);
        storePair(smb + YH + r1off + c * 2, smb + YL + r1off + c * 2, m[nb][2], m[nb][3]);
    }
    // ================= stage 5: We =================
    stage_sync();
    prefetchW(smb + WB1, GW6, 18432, tid);
    {
        float d[8][4] = {};
        mma_stage<64>(smb + YH, smb + YL, WSB, smb + WB0, d, warp, lane);
#pragma unroll
        for (int nb = 0; nb < 8; ++nb) {
            int c = 8 * nb + 2 * q;
            float b0 = be[c], b1 = be[c + 1];
            sig[nb][0] = sigmf(d[nb][0] + b0);
            sig[nb][1] = sigmf(d[nb][1] + b1);
            sig[nb][2] = sigmf(d[nb][2] + b0);
            sig[nb][3] = sigmf(d[nb][3] + b1);
        }
    }
    // ================= stage 6: Wa; res -> X[0:64], raw ht -> X[64:128] =================
    stage_sync();
    prefetchW(smb + WB0, GW7, 36864, tid);
    {
        float d[8][4] = {};
        mma_stage<64>(smb + YH, smb + YL, WSB, smb + WB1, d, warp, lane);
        const uint32_t x0 = (uint32_t)R0 * XSB, x1 = (uint32_t)R1 * XSB;
#pragma unroll
        for (int nb = 0; nb < 8; ++nb) {
            int c = 8 * nb + 2 * q;
            float b0 = ba[c], b1 = ba[c + 1];
            float res00 = m[nb][0] - eav0 * sig[nb][0] * m[nb][0] + eav0 * tanhf(d[nb][0] + b0);
            float res01 = m[nb][1] - eav0 * sig[nb][1] * m[nb][1] + eav0 * tanhf(d[nb][1] + b1);
            float res10 = m[nb][2] - eav1 * sig[nb][2] * m[nb][2] + eav1 * tanhf(d[nb][2] + b0);
            float res11 = m[nb][3] - eav1 * sig[nb][3] * m[nb][3] + eav1 * tanhf(d[nb][3] + b1);
            storePair(smb + XH + x0 + c * 2, smb + XL + x0 + c * 2, res00, res01);
            storePair(smb + XH + x1 + c * 2, smb + XL + x1 + c * 2, res10, res11);
            storePair(smb + XH + x0 + (64 + c) * 2, smb + XL + x0 + (64 + c) * 2, hp0[c], hp0[c + 1]);
            storePair(smb + XH + x1 + (64 + c) * 2, smb + XL + x1 + (64 + c) * 2, hp1[c], hp1[c + 1]);
        }
    }
    // ================= stage 7: GRU r =================
    stage_sync();
    prefetchW(smb + WB1, GW8, 36864, tid);
    {
        float d[8][4] = {};
        mma_stage<128>(smb + XH, smb + XL, XSB, smb + WB0, d, warp, lane);
#pragma unroll
        for (int nb = 0; nb < 8; ++nb) {
            int c = 8 * nb + 2 * q;
            float b0 = bih[c] + bhh[c], b1 = bih[c + 1] + bhh[c + 1];
            rg[nb][0] = sigmf(d[nb][0] + b0);
            rg[nb][1] = sigmf(d[nb][1] + b1);
            rg[nb][2] = sigmf(d[nb][2] + b0);
            rg[nb][3] = sigmf(d[nb][3] + b1);
        }
    }
    // ================= stage 8: GRU z =================
    stage_sync();
    prefetchW(smb + WB0, GW9, 18432, tid);
    {
        float d[8][4] = {};
        mma_stage<128>(smb + XH, smb + XL, XSB, smb + WB1, d, warp, lane);
#pragma unroll
        for (int nb = 0; nb < 8; ++nb) {
            int c = 8 * nb + 2 * q;
            float b0 = bih[64 + c] + bhh[64 + c], b1 = bih[64 + c + 1] + bhh[64 + c + 1];
            zg[nb][0] = sigmf(d[nb][0] + b0);
            zg[nb][1] = sigmf(d[nb][1] + b1);
            zg[nb][2] = sigmf(d[nb][2] + b0);
            zg[nb][3] = sigmf(d[nb][3] + b1);
        }
    }
    // ================= stage 9: in_ = res @ Wih_n =================
    stage_sync();
    prefetchW(smb + WB1, GW10, 18432, tid);
    {
        float d[8][4] = {};
        mma_stage<64>(smb + XH, smb + XL, XSB, smb + WB0, d, warp, lane);
#pragma unroll
        for (int nb = 0; nb < 8; ++nb) {
            int c = 8 * nb + 2 * q;
            inv[nb][0] = d[nb][0] + bih[128 + c];
            inv[nb][1] = d[nb][1] + bih[128 + c + 1];
            inv[nb][2] = d[nb][2] + bih[128 + c];
            inv[nb][3] = d[nb][3] + bih[128 + c + 1];
        }
    }
    // ================= stage 10: hn = ht @ Whh_n; GRU fuse; output dot =================
    stage_sync();
    {
        float d[8][4] = {};
        mma_stage<64>(smb + XH + 128, smb + XL + 128, XSB, smb + WB1, d, warp, lane);
        float p0 = 0.f, p1 = 0.f;
#pragma unroll
        for (int nb = 0; nb < 8; ++nb) {
            int c = 8 * nb + 2 * q;
            float b0 = bhh[128 + c], b1 = bhh[128 + c + 1];
            float w0 = Wp[c], w1 = Wp[c + 1];
            float n00 = tanhf(inv[nb][0] + rg[nb][0] * (d[nb][0] + b0));
            float n01 = tanhf(inv[nb][1] + rg[nb][1] * (d[nb][1] + b1));
            float n10 = tanhf(inv[nb][2] + rg[nb][2] * (d[nb][2] + b0));
            float n11 = tanhf(inv[nb][3] + rg[nb][3] * (d[nb][3] + b1));
            float h00 = (1.f - zg[nb][0]) * n00 + zg[nb][0] * hp0[c];
            float h01 = (1.f - zg[nb][1]) * n01 + zg[nb][1] * hp0[c + 1];
            float h10 = (1.f - zg[nb][2]) * n10 + zg[nb][2] * hp1[c];
            float h11 = (1.f - zg[nb][3]) * n11 + zg[nb][3] * hp1[c + 1];
            p0 = fmaf(h00, w0, fmaf(h01, w1, p0));
            p1 = fmaf(h10, w0, fmaf(h11, w1, p1));
        }
        // reduce across the 4 lanes (q=0..3) sharing each row
        p0 += __shfl_xor_sync(0xffffffffu, p0, 1);
        p0 += __shfl_xor_sync(0xffffffffu, p0, 2);
        p1 += __shfl_xor_sync(0xffffffffu, p1, 1);
        p1 += __shfl_xor_sync(0xffffffffu, p1, 2);
        if (q == 0) {
            out[r0 + R0] = sigmf(p0 + bp0);
            out[r0 + R1] = sigmf(p1 + bp0);
        }
    }
}

// ---------------- launch -----------------------------------------------------------------
extern "C" void kernel_launch(void* const* d_in, const int* in_sizes, int n_in,
                              void* d_out, int out_size) {
    const int*   qt     = (const int*)d_in[1];
    const float* ht     = (const float*)d_in[2];
    const float* onehot = (const float*)d_in[3];
    const float* kc     = (const float*)d_in[4];
    const float* graphs = (const float*)d_in[5];
    const float* nw     = (const float*)d_in[6];
    const float* Ws1    = (const float*)d_in[7];
    const float* bs1    = (const float*)d_in[8];
    const float* Ws2    = (const float*)d_in[9];
    const float* bs2    = (const float*)d_in[10];
    const float* Wn1    = (const float*)d_in[11];
    const float* bn1    = (const float*)d_in[12];
    const float* Wn2    = (const float*)d_in[13];
    const float* bn2    = (const float*)d_in[14];
    const float* ea     = (const float*)d_in[15];
    const float* We     = (const float*)d_in[16];
    const float* be     = (const float*)d_in[17];
    const float* Wa     = (const float*)d_in[18];
    const float* ba     = (const float*)d_in[19];
    const float* Wih    = (const float*)d_in[20];
    const float* bih    = (const float*)d_in[21];
    const float* Whh    = (const float*)d_in[22];
    const float* bhh    = (const float*)d_in[23];
    const float* Wp     = (const float*)d_in[24];
    const float* bp     = (const float*)d_in[25];
    float* out = (float*)d_out;

    cudaFuncSetAttribute(fused_kernel, cudaFuncAttributeMaxDynamicSharedMemorySize, SMEM_DYN);

    adj_kernel<<<2, 1024>>>(qt, onehot, graphs);
    prep_kernel<<<(57344 + 255) / 256, 256>>>(Wn1, Wn2, We, Wa, Wih, Whh);
    fused_kernel<<<2048, 256, SMEM_DYN>>>(
        qt, ht, onehot, kc, nw, Ws1, bs1, Ws2, bs2, bn1, bn2,
        ea, be, ba, bih, bhh, Wp, bp, out);
}

// round 6
// speedup vs baseline: 2.5178x; 1.0559x over previous
#include <cuda_runtime.h>
#include <cuda_fp16.h>
#include <cstdint>
#include <math.h>

constexpr int C = 1024;

// ---- smem byte offsets ----
constexpr uint32_t XB   = 0;        // X: 128 rows x 272B (128 halfs + pad)
constexpr uint32_t YB   = 34816;    // Y: 128 rows x 272B
constexpr uint32_t W0   = 69632;    // weight buffer 0 (69632B max)
constexpr uint32_t W1   = 139264;   // weight buffer 1
constexpr uint32_t MISC = 208896;
constexpr uint32_t SMEM_DYN = 209952;
constexpr uint32_t RSB = 272;       // row stride bytes everywhere

// ---- weight arena: per-stage [K rows x 128 cols] fp16 hi plane then lo plane ----
constexpr uint32_t GA1 = 0;        // nb1_0|nb1_1      K=128 (69632B)
constexpr uint32_t GA2 = 69632;    // blockdiag nb2    K=128
constexpr uint32_t GA3 = 139264;   // We|Wa            K=64  (34816B)
constexpr uint32_t GA4 = 174080;   // GRU r|z          K=128
constexpr uint32_t GA5 = 243712;   // blockdiag in|hn  K=128
__device__ __align__(16) unsigned char g_wb[313344];
__device__ float g_adj[2 * C];

__device__ __forceinline__ float clip5f(float v) { return fminf(fmaxf(v, -5.f), 5.f); }
__device__ __forceinline__ float sigmf(float v) { return 1.f / (1.f + expf(-v)); }

__device__ __forceinline__ uint32_t smem_u32(const void* p) {
    uint32_t a;
    asm("{ .reg .u64 t; cvta.to.shared.u64 t, %1; cvt.u32.u64 %0, t; }" : "=r"(a) : "l"(p));
    return a;
}
__device__ __forceinline__ void ldsm4(uint32_t* r, uint32_t a) {
    asm volatile("ldmatrix.sync.aligned.m8n8.x4.shared.b16 {%0,%1,%2,%3}, [%4];"
                 : "=r"(r[0]), "=r"(r[1]), "=r"(r[2]), "=r"(r[3]) : "r"(a));
}
__device__ __forceinline__ void ldsm4t(uint32_t* r, uint32_t a) {
    asm volatile("ldmatrix.sync.aligned.m8n8.x4.trans.shared.b16 {%0,%1,%2,%3}, [%4];"
                 : "=r"(r[0]), "=r"(r[1]), "=r"(r[2]), "=r"(r[3]) : "r"(a));
}
__device__ __forceinline__ void mma16816(float* d, const uint32_t* a, const uint32_t* b) {
    asm volatile("mma.sync.aligned.m16n8k16.row.col.f32.f16.f16.f32 "
                 "{%0,%1,%2,%3}, {%4,%5,%6,%7}, {%8,%9}, {%0,%1,%2,%3};"
                 : "+f"(d[0]), "+f"(d[1]), "+f"(d[2]), "+f"(d[3])
                 : "r"(a[0]), "r"(a[1]), "r"(a[2]), "r"(a[3]), "r"(b[0]), "r"(b[1]));
}
__device__ __forceinline__ void cpa16(uint32_t dst, const void* src) {
    asm volatile("cp.async.cg.shared.global [%0], [%1], 16;" :: "r"(dst), "l"(src));
}
__device__ __forceinline__ void cpa_commit() { asm volatile("cp.async.commit_group;" ::: "memory"); }
__device__ __forceinline__ void cpa_wait0()  { asm volatile("cp.async.wait_group 0;" ::: "memory"); }

// pack fp32 pair -> fp16x2, store to smem (f0 in low half)
__device__ __forceinline__ void storeH2(uint32_t addr, float f0, float f1) {
    uint32_t h;
    asm("cvt.rn.f16x2.f32 %0, %1, %2;" : "=r"(h) : "f"(f1), "f"(f0));
    asm volatile("st.shared.b32 [%0], %1;" :: "r"(addr), "r"(h));
}

// ---------------- adj precompute (sparse) ------------------------------------------------
__global__ void adj_kernel(const int* __restrict__ qt, const float* __restrict__ onehot,
                           const float* __restrict__ graphs) {
    __shared__ int nnz;
    __shared__ int idxs[1024];
    __shared__ float wts[1024];
    __shared__ float denom;
    int d = threadIdx.x, k = blockIdx.x;
    const float* a0 = onehot + (size_t)qt[0] * C;
    float a = a0[d];
    if (d == 0) nnz = 0;
    __syncthreads();
    if (a != 0.f) { int p = atomicAdd(&nnz, 1); idxs[p] = d; wts[p] = a; }
    __syncthreads();
    if (d == 0) {
        float s = 0.f;
        for (int i = 0; i < nnz; ++i) s += wts[i];
        denom = fmaxf(s, 1.f);
    }
    __syncthreads();
    float s = 0.f;
    int m = nnz;
    for (int i = 0; i < m; ++i)
        s = fmaf(wts[i], graphs[((size_t)k * C + idxs[i]) * C + d], s);
    g_adj[k * C + d] = clip5f(s / denom);
}

// ---------------- weight prep: merged [K,128] fp16 hi/lo images --------------------------
__global__ void prep_kernel(const float* __restrict__ Wn1, const float* __restrict__ Wn2,
                            const float* __restrict__ We,  const float* __restrict__ Wa,
                            const float* __restrict__ Wih, const float* __restrict__ Whh) {
    int i = blockIdx.x * 256 + threadIdx.x;
    if (i >= 73728) return;
    int j, K; uint32_t base; float w = 0.f;
    if (i < 16384) {       // S1: nb1_0 | nb1_1, K=128
        j = i; K = 128; base = GA1;
        int k = j >> 7, n = j & 127;
        if (n < 64) w = Wn1[(size_t)(128 + k) * 64 + n];
        else        w = Wn1[(size_t)(256 + 128 + k) * 64 + (n - 64)];
    } else if (i < 32768) { // S2: blockdiag(Wn2_0, Wn2_1), K=128
        j = i - 16384; K = 128; base = GA2;
        int k = j >> 7, n = j & 127;
        if (k < 64 && n < 64)        w = Wn2[(size_t)k * 64 + n];
        else if (k >= 64 && n >= 64) w = Wn2[(size_t)k * 64 + (n - 64)];  // (64+(k-64)) = k
    } else if (i < 40960) { // S3: We | Wa, K=64
        j = i - 32768; K = 64; base = GA3;
        int k = j >> 7, n = j & 127;
        w = (n < 64) ? We[(size_t)k * 64 + n] : Wa[(size_t)k * 64 + (n - 64)];
    } else if (i < 57344) { // S4: [Wih_r;Whh_r] | [Wih_z;Whh_z], K=128
        j = i - 40960; K = 128; base = GA4;
        int k = j >> 7, n = j & 127;
        w = (k < 64) ? Wih[(size_t)k * 192 + n] : Whh[(size_t)(k - 64) * 192 + n];
    } else {               // S5: blockdiag(Wih_n, Whh_n), K=128
        j = i - 57344; K = 128; base = GA5;
        int k = j >> 7, n = j & 127;
        if (k < 64 && n < 64)        w = Wih[(size_t)k * 192 + 128 + n];
        else if (k >= 64 && n >= 64) w = Whh[(size_t)(k - 64) * 192 + 128 + (n - 64)];
    }
    int k = j >> 7, n = j & 127;
    __half hi = __float2half_rn(w);
    __half lo = __float2half_rn(w - __half2float(hi));
    *(__half*)(g_wb + base + (uint32_t)k * RSB + n * 2) = hi;
    *(__half*)(g_wb + base + (uint32_t)K * RSB + (uint32_t)k * RSB + n * 2) = lo;
}

// ---------------- stage GEMM: D[128,128] = A[128,KD] @ W[KD,128], 2-pass fp16 ------------
template <int KD>
__device__ __forceinline__ void mma_stage(uint32_t aBase, uint32_t wbuf,
                                          float d[16][4], int warp, int lane) {
    const uint32_t wHi = wbuf, wLo = wbuf + KD * RSB;
    const int lrow = (lane & 7) + ((lane & 8) ? 8 : 0);
    const int lhi8 = (lane & 16) ? 8 : 0;
    const uint32_t aA = aBase + (uint32_t)(warp * 16 + lrow) * RSB + lhi8 * 2;
    const uint32_t wOff = (uint32_t)lrow * RSB + lhi8 * 2;
#pragma unroll
    for (int kc = 0; kc < KD / 16; ++kc) {
        uint32_t a[4];
        ldsm4(a, aA + kc * 32);
#pragma unroll
        for (int half = 0; half < 2; ++half) {
            uint32_t bh[4][4], bl[4][4];
#pragma unroll
            for (int p = 0; p < 4; ++p) {
                uint32_t off = wOff + (uint32_t)kc * 16 * RSB + (4 * half + p) * 32;
                ldsm4t(bh[p], wHi + off);
                ldsm4t(bl[p], wLo + off);
            }
#pragma unroll
            for (int n8 = 0; n8 < 8; ++n8) {
                const uint32_t* bhp = &bh[n8 >> 1][(n8 & 1) * 2];
                const uint32_t* blp = &bl[n8 >> 1][(n8 & 1) * 2];
                mma16816(d[8 * half + n8], a, bhp);
                mma16816(d[8 * half + n8], a, blp);
            }
        }
    }
}

__device__ __forceinline__ void prefetchW(uint32_t dst, uint32_t gsrc, int bytes, int tid) {
    const unsigned char* s = g_wb + gsrc;
    for (int o = tid * 16; o < bytes; o += 256 * 16) cpa16(dst + o, s + o);
    cpa_commit();
}

// ---------------- main fused kernel ------------------------------------------------------
__global__ void __launch_bounds__(256, 1)
fused_kernel(const int* __restrict__ qt, const float* __restrict__ ht,
             const float* __restrict__ onehot, const float* __restrict__ kc,
             const float* __restrict__ nwp,
             const float* __restrict__ Ws1, const float* __restrict__ bs1,
             const float* __restrict__ Ws2, const float* __restrict__ bs2,
             const float* __restrict__ bn1, const float* __restrict__ bn2,
             const float* __restrict__ ea,  const float* __restrict__ be,
             const float* __restrict__ ba,  const float* __restrict__ bih,
             const float* __restrict__ bhh, const float* __restrict__ Wp,
             const float* __restrict__ bp, float* __restrict__ out) {
    extern __shared__ __align__(16) char sm[];
    const uint32_t smb = smem_u32(sm);

    const int tid = threadIdx.x;
    const int warp = tid >> 5, lane = tid & 31;
    const int q = lane & 3, trow = lane >> 2;
    const int R0 = warp * 16 + trow, R1 = R0 + 8;
    const int r0 = blockIdx.x * 128;
    const int b  = r0 >> 10;
    const int cb0 = r0 & (C - 1);

    int* mcount = (int*)(sm + MISC);
    int* mrows  = (int*)(sm + MISC + 16);
    float* self1 = (float*)(sm + MISC + 528);
    float* selfo = (float*)(sm + MISC + 784);

    const float nw = fminf(fmaxf(nwp[0], 0.1f), 0.9f);
    const int qtb  = qt[b];
    const float bp0 = bp[0];
    const float adjA0 = g_adj[cb0 + R0], adjA1 = g_adj[cb0 + R1];
    const float adjB0 = g_adj[C + cb0 + R0], adjB1 = g_adj[C + cb0 + R1];
    const float eav0 = ea[cb0 + R0], eav1 = ea[cb0 + R1];
    const float* hp0 = ht + (size_t)(r0 + R0) * 64;
    const float* hp1 = ht + (size_t)(r0 + R1) * 64;

    if (tid == 0) *mcount = 0;
    __syncthreads();
    if (tid < 128 && onehot[(size_t)qtb * C + cb0 + tid] > 0.5f) {
        int p = atomicAdd(mcount, 1);
        mrows[p] = tid;
    }

    // ---- build X = [fp16(clip5 ht) | fp16(clip5 kc)] ----
    {
        int row = tid >> 1, half = tid & 1;
        const float* src = half ? (kc + (size_t)(cb0 + row) * 64) : (ht + (size_t)(r0 + row) * 64);
        uint32_t rowb = smb + XB + (uint32_t)row * RSB + (uint32_t)half * 128;
#pragma unroll
        for (int i = 0; i < 16; ++i) {
            float4 v = ((const float4*)src)[i];
            storeH2(rowb + i * 8,     clip5f(v.x), clip5f(v.y));
            storeH2(rowb + i * 8 + 4, clip5f(v.z), clip5f(v.w));
        }
    }
    prefetchW(smb + W0, GA1, 69632, tid);

    auto stage_sync = [&] { cpa_wait0(); __syncthreads(); };

    float m[8][4], rg[8][4], zg[8][4];
    const uint32_t y0 = smb + YB + (uint32_t)R0 * RSB, y1 = smb + YB + (uint32_t)R1 * RSB;
    const uint32_t x0 = smb + XB + (uint32_t)R0 * RSB, x1 = smb + XB + (uint32_t)R1 * RSB;

    // ================= S1: nb1_0 | nb1_1 =================
    stage_sync();
    prefetchW(smb + W1, GA2, 69632, tid);
    {
        float d[16][4] = {};
        mma_stage<128>(smb + XB, smb + W0, d, warp, lane);
#pragma unroll
        for (int nb = 0; nb < 16; ++nb) {
            int c = 8 * nb + 2 * q;
            float b0 = bn1[c], b1 = bn1[c + 1];   // bn1 flat (2,64) = 128
            storeH2(y0 + c * 2, fmaxf(d[nb][0] + b0, 0.f), fmaxf(d[nb][1] + b1, 0.f));
            storeH2(y1 + c * 2, fmaxf(d[nb][2] + b0, 0.f), fmaxf(d[nb][3] + b1, 0.f));
        }
    }
    // ================= S2: blockdiag nb2 =================
    stage_sync();
    prefetchW(smb + W0, GA3, 34816, tid);
    {
        float d[16][4] = {};
        mma_stage<128>(smb + YB, smb + W1, d, warp, lane);
        float wn = 1.f - nw;
#pragma unroll
        for (int nb = 0; nb < 8; ++nb) {
            int c = 8 * nb + 2 * q;
            float b00 = bn2[c], b01 = bn2[c + 1];
            float b10 = bn2[64 + c], b11 = bn2[64 + c + 1];
#pragma unroll
            for (int e = 0; e < 4; ++e) {
                float adjA = (e < 2) ? adjA0 : adjA1;
                float adjB = (e < 2) ? adjB0 : adjB1;
                float bb0 = (e & 1) ? b01 : b00;
                float bb1 = (e & 1) ? b11 : b10;
                float nb0 = fminf(fmaxf(d[nb][e] + bb0, 0.f), 5.f);
                float nb1 = fminf(fmaxf(d[nb + 8][e] + bb1, 0.f), 5.f);
                float t = clip5f(adjA * nb0);
                m[nb][e] = clip5f(nw * t + wn * adjB * nb1);
            }
        }
    }
    // ---- self path for masked rows (rare) ----
    __syncthreads();
    {
        int mc = *mcount;
        for (int mi = 0; mi < mc; ++mi) {
            int rr = mrows[mi];
            if (tid < 64) {
                const float* hrow = ht + (size_t)(r0 + rr) * 64;
                const float* krow = kc + (size_t)(cb0 + rr) * 64;
                float s = bs1[tid];
                for (int i = 0; i < 64; ++i) s = fmaf(hrow[i], Ws1[i * 64 + tid], s);
                for (int i = 0; i < 64; ++i) s = fmaf(krow[i], Ws1[(64 + i) * 64 + tid], s);
                self1[tid] = fmaxf(s, 0.f);
            }
            __syncthreads();
            if (tid < 64) {
                float s = bs2[tid];
                for (int i = 0; i < 64; ++i) s = fmaf(self1[i], Ws2[i * 64 + tid], s);
                selfo[tid] = fminf(fmaxf(s, 0.f), 10.f);
            }
            __syncthreads();
            if (R0 == rr)
#pragma unroll
                for (int nb = 0; nb < 8; ++nb) {
                    m[nb][0] = selfo[8 * nb + 2 * q];
                    m[nb][1] = selfo[8 * nb + 2 * q + 1];
                }
            if (R1 == rr)
#pragma unroll
                for (int nb = 0; nb < 8; ++nb) {
                    m[nb][2] = selfo[8 * nb + 2 * q];
                    m[nb][3] = selfo[8 * nb + 2 * q + 1];
                }
            __syncthreads();
        }
    }
    // store m -> Y[0:64] (A for S3)
#pragma unroll
    for (int nb = 0; nb < 8; ++nb) {
        int c = 8 * nb + 2 * q;
        storeH2(y0 + c * 2, m[nb][0], m[nb][1]);
        storeH2(y1 + c * 2, m[nb][2], m[nb][3]);
    }
    // ================= S3: We | Wa =================
    stage_sync();
    prefetchW(smb + W1, GA4, 69632, tid);
    {
        float d[16][4] = {};
        mma_stage<64>(smb + YB, smb + W0, d, warp, lane);
#pragma unroll
        for (int nb = 0; nb < 8; ++nb) {
            int c = 8 * nb + 2 * q;
            float be0 = be[c], be1 = be[c + 1];
            float ba0 = ba[c], ba1 = ba[c + 1];
            float res[4];
#pragma unroll
            for (int e = 0; e < 4; ++e) {
                float eav = (e < 2) ? eav0 : eav1;
                float sg = sigmf(d[nb][e] + ((e & 1) ? be1 : be0));
                float th = tanhf(d[nb + 8][e] + ((e & 1) ? ba1 : ba0));
                res[e] = m[nb][e] - eav * sg * m[nb][e] + eav * th;
            }
            storeH2(x0 + c * 2, res[0], res[1]);
            storeH2(x1 + c * 2, res[2], res[3]);
            storeH2(x0 + (64 + c) * 2, hp0[c], hp0[c + 1]);   // raw ht for hn
            storeH2(x1 + (64 + c) * 2, hp1[c], hp1[c + 1]);
        }
    }
    // ================= S4: GRU r | z =================
    stage_sync();
    prefetchW(smb + W0, GA5, 69632, tid);
    {
        float d[16][4] = {};
        mma_stage<128>(smb + XB, smb + W1, d, warp, lane);
#pragma unroll
        for (int nb = 0; nb < 8; ++nb) {
            int c = 8 * nb + 2 * q;
            float br0 = bih[c] + bhh[c], br1 = bih[c + 1] + bhh[c + 1];
            float bz0 = bih[64 + c] + bhh[64 + c], bz1 = bih[64 + c + 1] + bhh[64 + c + 1];
#pragma unroll
            for (int e = 0; e < 4; ++e) {
                rg[nb][e] = sigmf(d[nb][e] + ((e & 1) ? br1 : br0));
                zg[nb][e] = sigmf(d[nb + 8][e] + ((e & 1) ? bz1 : bz0));
            }
        }
    }
    // ================= S5: blockdiag in|hn ; GRU fuse ; output dot =================
    stage_sync();
    {
        float d[16][4] = {};
        mma_stage<128>(smb + XB, smb + W0, d, warp, lane);
        float p0 = 0.f, p1 = 0.f;
#pragma unroll
        for (int nb = 0; nb < 8; ++nb) {
            int c = 8 * nb + 2 * q;
            float bi0 = bih[128 + c], bi1 = bih[128 + c + 1];
            float bh0 = bhh[128 + c], bh1 = bhh[128 + c + 1];
            float w0 = Wp[c], w1 = Wp[c + 1];
            float n00 = tanhf(d[nb][0] + bi0 + rg[nb][0] * (d[nb + 8][0] + bh0));
            float n01 = tanhf(d[nb][1] + bi1 + rg[nb][1] * (d[nb + 8][1] + bh1));
            float n10 = tanhf(d[nb][2] + bi0 + rg[nb][2] * (d[nb + 8][2] + bh0));
            float n11 = tanhf(d[nb][3] + bi1 + rg[nb][3] * (d[nb + 8][3] + bh1));
            float h00 = (1.f - zg[nb][0]) * n00 + zg[nb][0] * hp0[c];
            float h01 = (1.f - zg[nb][1]) * n01 + zg[nb][1] * hp0[c + 1];
            float h10 = (1.f - zg[nb][2]) * n10 + zg[nb][2] * hp1[c];
            float h11 = (1.f - zg[nb][3]) * n11 + zg[nb][3] * hp1[c + 1];
            p0 = fmaf(h00, w0, fmaf(h01, w1, p0));
            p1 = fmaf(h10, w0, fmaf(h11, w1, p1));
        }
        p0 += __shfl_xor_sync(0xffffffffu, p0, 1);
        p0 += __shfl_xor_sync(0xffffffffu, p0, 2);
        p1 += __shfl_xor_sync(0xffffffffu, p1, 1);
        p1 += __shfl_xor_sync(0xffffffffu, p1, 2);
        if (q == 0) {
            out[r0 + R0] = sigmf(p0 + bp0);
            out[r0 + R1] = sigmf(p1 + bp0);
        }
    }
}

// ---------------- launch -----------------------------------------------------------------
extern "C" void kernel_launch(void* const* d_in, const int* in_sizes, int n_in,
                              void* d_out, int out_size) {
    const int*   qt     = (const int*)d_in[1];
    const float* ht     = (const float*)d_in[2];
    const float* onehot = (const float*)d_in[3];
    const float* kc     = (const float*)d_in[4];
    const float* graphs = (const float*)d_in[5];
    const float* nw     = (const float*)d_in[6];
    const float* Ws1    = (const float*)d_in[7];
    const float* bs1    = (const float*)d_in[8];
    const float* Ws2    = (const float*)d_in[9];
    const float* bs2    = (const float*)d_in[10];
    const float* Wn1    = (const float*)d_in[11];
    const float* bn1    = (const float*)d_in[12];
    const float* Wn2    = (const float*)d_in[13];
    const float* bn2    = (const float*)d_in[14];
    const float* ea     = (const float*)d_in[15];
    const float* We     = (const float*)d_in[16];
    const float* be     = (const float*)d_in[17];
    const float* Wa     = (const float*)d_in[18];
    const float* ba     = (const float*)d_in[19];
    const float* Wih    = (const float*)d_in[20];
    const float* bih    = (const float*)d_in[21];
    const float* Whh    = (const float*)d_in[22];
    const float* bhh    = (const float*)d_in[23];
    const float* Wp     = (const float*)d_in[24];
    const float* bp     = (const float*)d_in[25];
    float* out = (float*)d_out;

    cudaFuncSetAttribute(fused_kernel, cudaFuncAttributeMaxDynamicSharedMemorySize, SMEM_DYN);

    adj_kernel<<<2, 1024>>>(qt, onehot, graphs);
    prep_kernel<<<(73728 + 255) / 256, 256>>>(Wn1, Wn2, We, Wa, Wih, Whh);
    fused_kernel<<<2048, 256, SMEM_DYN>>>(
        qt, ht, onehot, kc, nw, Ws1, bs1, Ws2, bs2, bn1, bn2,
        ea, be, ba, bih, bhh, Wp, bp, out);
}

// round 7
// speedup vs baseline: 4.1046x; 1.6302x over previous
#include <cuda_runtime.h>
#include <cuda_fp16.h>
#include <cstdint>
#include <math.h>

constexpr int C = 1024;

// ---- smem byte offsets ----
constexpr uint32_t XB   = 0;        // X: 128 rows x 272B (128 halfs + pad), in-place all stages
constexpr uint32_t W0   = 34816;    // weight buffer 0 (34816B max)
constexpr uint32_t W1   = 69632;    // weight buffer 1
constexpr uint32_t MISC = 104448;
constexpr uint32_t SMEM_DYN = 105504;
constexpr uint32_t RSB = 272;       // row stride bytes everywhere

// ---- weight arena: per-stage [K rows x 128 cols] fp16 (single plane) ----
constexpr uint32_t GA1 = 0;        // nb1_0|nb1_1      K=128 (34816B)
constexpr uint32_t GA2 = 34816;    // blockdiag nb2    K=128
constexpr uint32_t GA3 = 69632;    // We|Wa            K=64  (17408B)
constexpr uint32_t GA4 = 87040;    // GRU r|z          K=128
constexpr uint32_t GA5 = 121856;   // blockdiag in|hn  K=128
__device__ __align__(16) unsigned char g_wb[156672];
__device__ float g_adj[2 * C];

__device__ __forceinline__ float clip5f(float v) { return fminf(fmaxf(v, -5.f), 5.f); }
__device__ __forceinline__ float sigmf(float v) { return 1.f / (1.f + expf(-v)); }

__device__ __forceinline__ uint32_t smem_u32(const void* p) {
    uint32_t a;
    asm("{ .reg .u64 t; cvta.to.shared.u64 t, %1; cvt.u32.u64 %0, t; }" : "=r"(a) : "l"(p));
    return a;
}
__device__ __forceinline__ void ldsm4(uint32_t* r, uint32_t a) {
    asm volatile("ldmatrix.sync.aligned.m8n8.x4.shared.b16 {%0,%1,%2,%3}, [%4];"
                 : "=r"(r[0]), "=r"(r[1]), "=r"(r[2]), "=r"(r[3]) : "r"(a));
}
__device__ __forceinline__ void ldsm4t(uint32_t* r, uint32_t a) {
    asm volatile("ldmatrix.sync.aligned.m8n8.x4.trans.shared.b16 {%0,%1,%2,%3}, [%4];"
                 : "=r"(r[0]), "=r"(r[1]), "=r"(r[2]), "=r"(r[3]) : "r"(a));
}
__device__ __forceinline__ void mma16816(float* d, const uint32_t* a, const uint32_t* b) {
    asm volatile("mma.sync.aligned.m16n8k16.row.col.f32.f16.f16.f32 "
                 "{%0,%1,%2,%3}, {%4,%5,%6,%7}, {%8,%9}, {%0,%1,%2,%3};"
                 : "+f"(d[0]), "+f"(d[1]), "+f"(d[2]), "+f"(d[3])
                 : "r"(a[0]), "r"(a[1]), "r"(a[2]), "r"(a[3]), "r"(b[0]), "r"(b[1]));
}
__device__ __forceinline__ void cpa16(uint32_t dst, const void* src) {
    asm volatile("cp.async.cg.shared.global [%0], [%1], 16;" :: "r"(dst), "l"(src));
}
__device__ __forceinline__ void cpa_commit() { asm volatile("cp.async.commit_group;" ::: "memory"); }
__device__ __forceinline__ void cpa_wait0()  { asm volatile("cp.async.wait_group 0;" ::: "memory"); }

// pack fp32 pair -> fp16x2 (f0 in low half)
__device__ __forceinline__ uint32_t packH2(float f0, float f1) {
    uint32_t h;
    asm("cvt.rn.f16x2.f32 %0, %1, %2;" : "=r"(h) : "f"(f1), "f"(f0));
    return h;
}
__device__ __forceinline__ void storeH2(uint32_t addr, float f0, float f1) {
    uint32_t h = packH2(f0, f1);
    asm volatile("st.shared.b32 [%0], %1;" :: "r"(addr), "r"(h));
}

// ---------------- adj precompute (sparse) ------------------------------------------------
__global__ void adj_kernel(const int* __restrict__ qt, const float* __restrict__ onehot,
                           const float* __restrict__ graphs) {
    __shared__ int nnz;
    __shared__ int idxs[1024];
    __shared__ float wts[1024];
    __shared__ float denom;
    int d = threadIdx.x, k = blockIdx.x;
    const float* a0 = onehot + (size_t)qt[0] * C;
    float a = a0[d];
    if (d == 0) nnz = 0;
    __syncthreads();
    if (a != 0.f) { int p = atomicAdd(&nnz, 1); idxs[p] = d; wts[p] = a; }
    __syncthreads();
    if (d == 0) {
        float s = 0.f;
        for (int i = 0; i < nnz; ++i) s += wts[i];
        denom = fmaxf(s, 1.f);
    }
    __syncthreads();
    float s = 0.f;
    int m = nnz;
    for (int i = 0; i < m; ++i)
        s = fmaf(wts[i], graphs[((size_t)k * C + idxs[i]) * C + d], s);
    g_adj[k * C + d] = clip5f(s / denom);
}

// ---------------- weight prep: merged [K,128] fp16 images --------------------------------
__global__ void prep_kernel(const float* __restrict__ Wn1, const float* __restrict__ Wn2,
                            const float* __restrict__ We,  const float* __restrict__ Wa,
                            const float* __restrict__ Wih, const float* __restrict__ Whh) {
    int i = blockIdx.x * 256 + threadIdx.x;
    if (i >= 73728) return;
    int j; uint32_t base; float w = 0.f;
    if (i < 16384) {       // S1: nb1_0 | nb1_1, K=128
        j = i; base = GA1;
        int k = j >> 7, n = j & 127;
        if (n < 64) w = Wn1[(size_t)(128 + k) * 64 + n];
        else        w = Wn1[(size_t)(256 + 128 + k) * 64 + (n - 64)];
    } else if (i < 32768) { // S2: blockdiag(Wn2_0, Wn2_1), K=128
        j = i - 16384; base = GA2;
        int k = j >> 7, n = j & 127;
        if (k < 64 && n < 64)        w = Wn2[(size_t)k * 64 + n];
        else if (k >= 64 && n >= 64) w = Wn2[(size_t)k * 64 + (n - 64)];
    } else if (i < 40960) { // S3: We | Wa, K=64
        j = i - 32768; base = GA3;
        int k = j >> 7, n = j & 127;
        w = (n < 64) ? We[(size_t)k * 64 + n] : Wa[(size_t)k * 64 + (n - 64)];
    } else if (i < 57344) { // S4: [Wih_r;Whh_r] | [Wih_z;Whh_z], K=128
        j = i - 40960; base = GA4;
        int k = j >> 7, n = j & 127;
        w = (k < 64) ? Wih[(size_t)k * 192 + n] : Whh[(size_t)(k - 64) * 192 + n];
    } else {               // S5: blockdiag(Wih_n, Whh_n), K=128
        j = i - 57344; base = GA5;
        int k = j >> 7, n = j & 127;
        if (k < 64 && n < 64)        w = Wih[(size_t)k * 192 + 128 + n];
        else if (k >= 64 && n >= 64) w = Whh[(size_t)(k - 64) * 192 + 128 + (n - 64)];
    }
    int k = j >> 7, n = j & 127;
    *(__half*)(g_wb + base + (uint32_t)k * RSB + n * 2) = __float2half_rn(w);
}

// ---------------- stage GEMM: D[128,128] = A[128,KD] @ W[KD,128], fp16 single pass -------
template <int KD>
__device__ __forceinline__ void mma_stage(uint32_t aBase, uint32_t wbuf,
                                          float d[16][4], int warp, int lane) {
    const int lrow = (lane & 7) + ((lane & 8) ? 8 : 0);
    const int lhi8 = (lane & 16) ? 8 : 0;
    const uint32_t aA = aBase + (uint32_t)(warp * 16 + lrow) * RSB + lhi8 * 2;
    const uint32_t wOff = wbuf + (uint32_t)lrow * RSB + lhi8 * 2;
#pragma unroll
    for (int kc = 0; kc < KD / 16; ++kc) {
        uint32_t a[4];
        ldsm4(a, aA + kc * 32);
#pragma unroll
        for (int half = 0; half < 2; ++half) {
            uint32_t bh[4][4];
#pragma unroll
            for (int p = 0; p < 4; ++p)
                ldsm4t(bh[p], wOff + (uint32_t)kc * 16 * RSB + (4 * half + p) * 32);
#pragma unroll
            for (int n8 = 0; n8 < 8; ++n8)
                mma16816(d[8 * half + n8], a, &bh[n8 >> 1][(n8 & 1) * 2]);
        }
    }
}

__device__ __forceinline__ void prefetchW(uint32_t dst, uint32_t gsrc, int bytes, int tid) {
    const unsigned char* s = g_wb + gsrc;
    for (int o = tid * 16; o < bytes; o += 256 * 16) cpa16(dst + o, s + o);
    cpa_commit();
}

// ---------------- main fused kernel ------------------------------------------------------
__global__ void __launch_bounds__(256, 2)
fused_kernel(const int* __restrict__ qt, const float* __restrict__ ht,
             const float* __restrict__ onehot, const float* __restrict__ kc,
             const float* __restrict__ nwp,
             const float* __restrict__ Ws1, const float* __restrict__ bs1,
             const float* __restrict__ Ws2, const float* __restrict__ bs2,
             const float* __restrict__ bn1, const float* __restrict__ bn2,
             const float* __restrict__ ea,  const float* __restrict__ be,
             const float* __restrict__ ba,  const float* __restrict__ bih,
             const float* __restrict__ bhh, const float* __restrict__ Wp,
             const float* __restrict__ bp, float* __restrict__ out) {
    extern __shared__ __align__(16) char sm[];
    const uint32_t smb = smem_u32(sm);

    const int tid = threadIdx.x;
    const int warp = tid >> 5, lane = tid & 31;
    const int q = lane & 3, trow = lane >> 2;
    const int R0 = warp * 16 + trow, R1 = R0 + 8;
    const int r0 = blockIdx.x * 128;
    const int b  = r0 >> 10;
    const int cb0 = r0 & (C - 1);

    int* mcount = (int*)(sm + MISC);
    int* mrows  = (int*)(sm + MISC + 16);
    float* self1 = (float*)(sm + MISC + 528);
    float* selfo = (float*)(sm + MISC + 784);

    const float nw = fminf(fmaxf(nwp[0], 0.1f), 0.9f);
    const int qtb  = qt[b];
    const float bp0 = bp[0];
    const float adjA0 = g_adj[cb0 + R0], adjA1 = g_adj[cb0 + R1];
    const float adjB0 = g_adj[C + cb0 + R0], adjB1 = g_adj[C + cb0 + R1];
    const float eav0 = ea[cb0 + R0], eav1 = ea[cb0 + R1];
    const float* hp0 = ht + (size_t)(r0 + R0) * 64;
    const float* hp1 = ht + (size_t)(r0 + R1) * 64;

    if (tid == 0) *mcount = 0;
    __syncthreads();
    if (tid < 128 && onehot[(size_t)qtb * C + cb0 + tid] > 0.5f) {
        int p = atomicAdd(mcount, 1);
        mrows[p] = tid;
    }

    // ---- build X = [fp16(clip5 ht) | fp16(clip5 kc)] ----
    {
        int row = tid >> 1, half = tid & 1;
        const float* src = half ? (kc + (size_t)(cb0 + row) * 64) : (ht + (size_t)(r0 + row) * 64);
        uint32_t rowb = smb + XB + (uint32_t)row * RSB + (uint32_t)half * 128;
#pragma unroll
        for (int i = 0; i < 16; ++i) {
            float4 v = ((const float4*)src)[i];
            storeH2(rowb + i * 8,     clip5f(v.x), clip5f(v.y));
            storeH2(rowb + i * 8 + 4, clip5f(v.z), clip5f(v.w));
        }
    }
    prefetchW(smb + W0, GA1, 34816, tid);

    auto stage_sync = [&] { cpa_wait0(); __syncthreads(); };

    float m[8][4];
    uint32_t rgp[8][2], zgp[8][2];   // packed fp16x2 gates
    const uint32_t x0 = smb + XB + (uint32_t)R0 * RSB, x1 = smb + XB + (uint32_t)R1 * RSB;

    // ================= S1: nb1_0 | nb1_1 (in-place X) =================
    stage_sync();
    prefetchW(smb + W1, GA2, 34816, tid);
    {
        float d[16][4] = {};
        mma_stage<128>(smb + XB, smb + W0, d, warp, lane);
#pragma unroll
        for (int nb = 0; nb < 16; ++nb) {
            int c = 8 * nb + 2 * q;
            float b0 = bn1[c], b1 = bn1[c + 1];
            storeH2(x0 + c * 2, fmaxf(d[nb][0] + b0, 0.f), fmaxf(d[nb][1] + b1, 0.f));
            storeH2(x1 + c * 2, fmaxf(d[nb][2] + b0, 0.f), fmaxf(d[nb][3] + b1, 0.f));
        }
    }
    // ================= S2: blockdiag nb2 =================
    stage_sync();
    prefetchW(smb + W0, GA3, 17408, tid);
    {
        float d[16][4] = {};
        mma_stage<128>(smb + XB, smb + W1, d, warp, lane);
        float wn = 1.f - nw;
#pragma unroll
        for (int nb = 0; nb < 8; ++nb) {
            int c = 8 * nb + 2 * q;
            float b00 = bn2[c], b01 = bn2[c + 1];
            float b10 = bn2[64 + c], b11 = bn2[64 + c + 1];
#pragma unroll
            for (int e = 0; e < 4; ++e) {
                float adjA = (e < 2) ? adjA0 : adjA1;
                float adjB = (e < 2) ? adjB0 : adjB1;
                float bb0 = (e & 1) ? b01 : b00;
                float bb1 = (e & 1) ? b11 : b10;
                float nb0 = fminf(fmaxf(d[nb][e] + bb0, 0.f), 5.f);
                float nb1 = fminf(fmaxf(d[nb + 8][e] + bb1, 0.f), 5.f);
                float t = clip5f(adjA * nb0);
                m[nb][e] = clip5f(nw * t + wn * adjB * nb1);
            }
        }
    }
    // ---- self path for masked rows (rare) ----
    __syncthreads();
    {
        int mc = *mcount;
        for (int mi = 0; mi < mc; ++mi) {
            int rr = mrows[mi];
            if (tid < 64) {
                const float* hrow = ht + (size_t)(r0 + rr) * 64;
                const float* krow = kc + (size_t)(cb0 + rr) * 64;
                float s = bs1[tid];
                for (int i = 0; i < 64; ++i) s = fmaf(hrow[i], Ws1[i * 64 + tid], s);
                for (int i = 0; i < 64; ++i) s = fmaf(krow[i], Ws1[(64 + i) * 64 + tid], s);
                self1[tid] = fmaxf(s, 0.f);
            }
            __syncthreads();
            if (tid < 64) {
                float s = bs2[tid];
                for (int i = 0; i < 64; ++i) s = fmaf(self1[i], Ws2[i * 64 + tid], s);
                selfo[tid] = fminf(fmaxf(s, 0.f), 10.f);
            }
            __syncthreads();
            if (R0 == rr)
#pragma unroll
                for (int nb = 0; nb < 8; ++nb) {
                    m[nb][0] = selfo[8 * nb + 2 * q];
                    m[nb][1] = selfo[8 * nb + 2 * q + 1];
                }
            if (R1 == rr)
#pragma unroll
                for (int nb = 0; nb < 8; ++nb) {
                    m[nb][2] = selfo[8 * nb + 2 * q];
                    m[nb][3] = selfo[8 * nb + 2 * q + 1];
                }
            __syncthreads();
        }
    }
    // store m -> X[0:64] (A for S3; cols 64..127 stale but unused at K=64)
#pragma unroll
    for (int nb = 0; nb < 8; ++nb) {
        int c = 8 * nb + 2 * q;
        storeH2(x0 + c * 2, m[nb][0], m[nb][1]);
        storeH2(x1 + c * 2, m[nb][2], m[nb][3]);
    }
    // ================= S3: We | Wa; X := [res | raw ht] =================
    stage_sync();
    prefetchW(smb + W1, GA4, 34816, tid);
    {
        float d[16][4] = {};
        mma_stage<64>(smb + XB, smb + W0, d, warp, lane);
#pragma unroll
        for (int nb = 0; nb < 8; ++nb) {
            int c = 8 * nb + 2 * q;
            float be0 = be[c], be1 = be[c + 1];
            float ba0 = ba[c], ba1 = ba[c + 1];
            float res[4];
#pragma unroll
            for (int e = 0; e < 4; ++e) {
                float eav = (e < 2) ? eav0 : eav1;
                float sg = sigmf(d[nb][e] + ((e & 1) ? be1 : be0));
                float th = tanhf(d[nb + 8][e] + ((e & 1) ? ba1 : ba0));
                res[e] = m[nb][e] - eav * sg * m[nb][e] + eav * th;
            }
            storeH2(x0 + c * 2, res[0], res[1]);
            storeH2(x1 + c * 2, res[2], res[3]);
            storeH2(x0 + (64 + c) * 2, hp0[c], hp0[c + 1]);
            storeH2(x1 + (64 + c) * 2, hp1[c], hp1[c + 1]);
        }
    }
    // ================= S4: GRU r | z =================
    stage_sync();
    prefetchW(smb + W0, GA5, 34816, tid);
    {
        float d[16][4] = {};
        mma_stage<128>(smb + XB, smb + W1, d, warp, lane);
#pragma unroll
        for (int nb = 0; nb < 8; ++nb) {
            int c = 8 * nb + 2 * q;
            float br0 = bih[c] + bhh[c], br1 = bih[c + 1] + bhh[c + 1];
            float bz0 = bih[64 + c] + bhh[64 + c], bz1 = bih[64 + c + 1] + bhh[64 + c + 1];
            rgp[nb][0] = packH2(sigmf(d[nb][0] + br0), sigmf(d[nb][1] + br1));
            rgp[nb][1] = packH2(sigmf(d[nb][2] + br0), sigmf(d[nb][3] + br1));
            zgp[nb][0] = packH2(sigmf(d[nb + 8][0] + bz0), sigmf(d[nb + 8][1] + bz1));
            zgp[nb][1] = packH2(sigmf(d[nb + 8][2] + bz0), sigmf(d[nb + 8][3] + bz1));
        }
    }
    // ================= S5: blockdiag in|hn ; GRU fuse ; output dot =================
    stage_sync();
    {
        float d[16][4] = {};
        mma_stage<128>(smb + XB, smb + W0, d, warp, lane);
        float p0 = 0.f, p1 = 0.f;
#pragma unroll
        for (int nb = 0; nb < 8; ++nb) {
            int c = 8 * nb + 2 * q;
            float bi0 = bih[128 + c], bi1 = bih[128 + c + 1];
            float bh0 = bhh[128 + c], bh1 = bhh[128 + c + 1];
            float w0 = Wp[c], w1 = Wp[c + 1];
            float2 rg0 = __half22float2(*(__half2*)&rgp[nb][0]);
            float2 rg1 = __half22float2(*(__half2*)&rgp[nb][1]);
            float2 zg0 = __half22float2(*(__half2*)&zgp[nb][0]);
            float2 zg1 = __half22float2(*(__half2*)&zgp[nb][1]);
            float n00 = tanhf(d[nb][0] + bi0 + rg0.x * (d[nb + 8][0] + bh0));
            float n01 = tanhf(d[nb][1] + bi1 + rg0.y * (d[nb + 8][1] + bh1));
            float n10 = tanhf(d[nb][2] + bi0 + rg1.x * (d[nb + 8][2] + bh0));
            float n11 = tanhf(d[nb][3] + bi1 + rg1.y * (d[nb + 8][3] + bh1));
            float h00 = (1.f - zg0.x) * n00 + zg0.x * hp0[c];
            float h01 = (1.f - zg0.y) * n01 + zg0.y * hp0[c + 1];
            float h10 = (1.f - zg1.x) * n10 + zg1.x * hp1[c];
            float h11 = (1.f - zg1.y) * n11 + zg1.y * hp1[c + 1];
            p0 = fmaf(h00, w0, fmaf(h01, w1, p0));
            p1 = fmaf(h10, w0, fmaf(h11, w1, p1));
        }
        p0 += __shfl_xor_sync(0xffffffffu, p0, 1);
        p0 += __shfl_xor_sync(0xffffffffu, p0, 2);
        p1 += __shfl_xor_sync(0xffffffffu, p1, 1);
        p1 += __shfl_xor_sync(0xffffffffu, p1, 2);
        if (q == 0) {
            out[r0 + R0] = sigmf(p0 + bp0);
            out[r0 + R1] = sigmf(p1 + bp0);
        }
    }
}

// ---------------- launch -----------------------------------------------------------------
extern "C" void kernel_launch(void* const* d_in, const int* in_sizes, int n_in,
                              void* d_out, int out_size) {
    const int*   qt     = (const int*)d_in[1];
    const float* ht     = (const float*)d_in[2];
    const float* onehot = (const float*)d_in[3];
    const float* kc     = (const float*)d_in[4];
    const float* graphs = (const float*)d_in[5];
    const float* nw     = (const float*)d_in[6];
    const float* Ws1    = (const float*)d_in[7];
    const float* bs1    = (const float*)d_in[8];
    const float* Ws2    = (const float*)d_in[9];
    const float* bs2    = (const float*)d_in[10];
    const float* Wn1    = (const float*)d_in[11];
    const float* bn1    = (const float*)d_in[12];
    const float* Wn2    = (const float*)d_in[13];
    const float* bn2    = (const float*)d_in[14];
    const float* ea     = (const float*)d_in[15];
    const float* We     = (const float*)d_in[16];
    const float* be     = (const float*)d_in[17];
    const float* Wa     = (const float*)d_in[18];
    const float* ba     = (const float*)d_in[19];
    const float* Wih    = (const float*)d_in[20];
    const float* bih    = (const float*)d_in[21];
    const float* Whh    = (const float*)d_in[22];
    const float* bhh    = (const float*)d_in[23];
    const float* Wp     = (const float*)d_in[24];
    const float* bp     = (const float*)d_in[25];
    float* out = (float*)d_out;

    cudaFuncSetAttribute(fused_kernel, cudaFuncAttributeMaxDynamicSharedMemorySize, SMEM_DYN);

    adj_kernel<<<2, 1024>>>(qt, onehot, graphs);
    prep_kernel<<<(73728 + 255) / 256, 256>>>(Wn1, Wn2, We, Wa, Wih, Whh);
    fused_kernel<<<2048, 256, SMEM_DYN>>>(
        qt, ht, onehot, kc, nw, Ws1, bs1, Ws2, bs2, bn1, bn2,
        ea, be, ba, bih, bhh, Wp, bp, out);
}